// round 11
// baseline (speedup 1.0000x reference)
#include <cuda_runtime.h>
#include <cstdint>

#define GENES 2048
#define HEADS 8
#define BATCH 16
#define NP 5           // Taylor powers 0..4 (|s|<~0.1 -> err ~1e-9; 0.3 -> 2e-5)
#define TPB  512
#define NVAL 9         // A1..A4, B0..B4   (A0 = 2048 exact)
#define NWARP (TPB / 32)

__constant__ float c_invfact[NP] = { 1.0f, 1.0f, 0.5f, 1.0f / 6.0f, 1.0f / 24.0f };

// ---------------- packed f32x2 helpers ----------------
__device__ __forceinline__ unsigned long long pk2(float lo, float hi) {
    unsigned long long r;
    asm("mov.b64 %0, {%1, %2};" : "=l"(r) : "f"(lo), "f"(hi));
    return r;
}
__device__ __forceinline__ void upk2(float& lo, float& hi, unsigned long long v) {
    asm("mov.b64 {%0, %1}, %2;" : "=f"(lo), "=f"(hi) : "l"(v));
}
__device__ __forceinline__ unsigned long long mul2(unsigned long long a, unsigned long long b) {
    unsigned long long r;
    asm("mul.rn.f32x2 %0, %1, %2;" : "=l"(r) : "l"(a), "l"(b));
    return r;
}
__device__ __forceinline__ unsigned long long add2(unsigned long long a, unsigned long long b) {
    unsigned long long r;
    asm("add.rn.f32x2 %0, %1, %2;" : "=l"(r) : "l"(a), "l"(b));
    return r;
}
__device__ __forceinline__ unsigned long long fma2(unsigned long long a, unsigned long long b,
                                                   unsigned long long c) {
    unsigned long long r;
    asm("fma.rn.f32x2 %0, %1, %2, %3;" : "=l"(r) : "l"(a), "l"(b), "l"(c));
    return r;
}
__device__ __forceinline__ uint32_t smem_u32(const void* p) {
    uint32_t a;
    asm("{ .reg .u64 t; cvta.to.shared.u64 t, %1; cvt.u32.u64 %0, t; }" : "=r"(a) : "l"(p));
    return a;
}
__device__ __forceinline__ void dsmem_store(uint32_t local_addr, uint32_t rank, float val) {
    asm volatile(
        "{ .reg .b32 r; mapa.shared::cluster.u32 r, %0, %1; st.shared::cluster.f32 [r], %2; }"
        :: "r"(local_addr), "r"(rank), "f"(val) : "memory");
}

// ---------------------------------------------------------------------------
// Cluster of 8 CTAs = one batch (rank = head), 512 threads (16 warps).
// Per thread: phase 1 = ONE float4 triple (4 genes) of the head's moment sweep
// (NP=5: A1..A4, B0..B4 packed f32x2); phase 2 = one gene x 4 heads.
// Entry-issued loads; pre-barrier exp; SHFL butterfly; DSMEM moment fan-out;
// single barrier.cluster; packed Horner; [2][256] smem head-half combine.
// ---------------------------------------------------------------------------
__global__ void __launch_bounds__(TPB, 1) __cluster_dims__(HEADS, 1, 1)
fused_attn_kernel(const float* __restrict__ x,
                  const float* __restrict__ WQ,
                  const float* __restrict__ WK,
                  const float* __restrict__ WV,
                  const float* __restrict__ W0,
                  float* __restrict__ out)
{
    const int b    = blockIdx.x >> 3;
    const int h    = blockIdx.x & 7;
    const int tid  = threadIdx.x;
    const int gl   = tid & 255;           // gene within this CTA's slice
    const int half = tid >> 8;            // 0: heads 0-3, 1: heads 4-7

    __shared__ float sRed[NWARP][NVAL];                   // per-warp partials
    __shared__ __align__(8) float sMomA[NP - 1][HEADS];   // A1..A4 per head
    __shared__ __align__(8) float sMomB[NP][HEADS];       // B0..B4 per head
    __shared__ float sW0[HEADS];
    __shared__ float sz[2][256];                          // head-half partials

    const float* __restrict__ xb = x + b * GENES;

    // -------- Entry: issue all global loads (one memory epoch) --------
    const int g = h * 256 + gl;
    const float xg = xb[g];
    float pq[4], pkk[4], pv[4];
#pragma unroll
    for (int e = 0; e < 4; e++) {
        const int H = half * 4 + e;
        pq[e]  = WQ[H * GENES + g];
        pkk[e] = WK[H * GENES + g];
        pv[e]  = WV[H * GENES + g];
    }
    if (tid < HEADS) sW0[tid] = W0[tid];

    const float4 xv = ((const float4*)xb)[tid];                 // 4 genes
    const float4 kv = ((const float4*)(WK + h * GENES))[tid];
    const float4 vv = ((const float4*)(WV + h * GENES))[tid];

    // -------- Phase 1: packed moments for 2 gene-pairs --------
    const unsigned long long xp0 = pk2(xv.x, xv.y);
    const unsigned long long xp1 = pk2(xv.z, xv.w);
    const unsigned long long k0  = mul2(xp0, pk2(kv.x, kv.y));
    const unsigned long long k1  = mul2(xp1, pk2(kv.z, kv.w));
    const unsigned long long v0  = mul2(xp0, pk2(vv.x, vv.y));
    const unsigned long long v1  = mul2(xp1, pk2(vv.z, vv.w));

    unsigned long long A[NP - 1], Bm[NP];
    Bm[0] = add2(v0, v1);
    {
        unsigned long long p0 = k0, p1 = k1;
#pragma unroll
        for (int n = 1; n < NP; n++) {
            A[n - 1] = add2(p0, p1);
            Bm[n]    = fma2(p0, v0, mul2(p1, v1));
            if (n < NP - 1) { p0 = mul2(p0, k0); p1 = mul2(p1, k1); }
        }
    }

    // -------- Exp-diagonal terms (MUFU overlaps the SHFLs below) --------
    float qs[4], ev[4];
#pragma unroll
    for (int e = 0; e < 4; e++) {
        qs[e] = xg * pq[e];
        ev[e] = __expf(qs[e] * (xg * pkk[e])) * (xg * pv[e]);
    }

    // -------- Fold packed halves -> 9 scalars; SHFL butterfly --------
    float vals[NVAL];
#pragma unroll
    for (int n = 0; n < NP - 1; n++) {
        float lo, hi; upk2(lo, hi, A[n]);
        vals[n] = lo + hi;
    }
#pragma unroll
    for (int n = 0; n < NP; n++) {
        float lo, hi; upk2(lo, hi, Bm[n]);
        vals[NP - 1 + n] = lo + hi;
    }
#pragma unroll
    for (int i = 0; i < NVAL; i++) {
#pragma unroll
        for (int off = 16; off > 0; off >>= 1)
            vals[i] += __shfl_xor_sync(0xFFFFFFFFu, vals[i], off);
    }

    const int w    = tid >> 5;
    const int lane = tid & 31;
    if (lane < NVAL) {
        float s;
        switch (lane) {
            case 0:  s = vals[0]; break;
            case 1:  s = vals[1]; break;
            case 2:  s = vals[2]; break;
            case 3:  s = vals[3]; break;
            case 4:  s = vals[4]; break;
            case 5:  s = vals[5]; break;
            case 6:  s = vals[6]; break;
            case 7:  s = vals[7]; break;
            default: s = vals[8]; break;
        }
        sRed[w][lane] = s;
    }
    __syncthreads();

    // -------- 9 threads: sum 16 warps, scale, DSMEM fan-out to 8 CTAs -------
    if (tid < NVAL) {
        float s = 0.0f;
#pragma unroll
        for (int ww = 0; ww < NWARP; ww++) s += sRed[ww][tid];
        float scaled;
        uint32_t addr;
        if (tid < NP - 1) {                               // A_{tid+1}
            scaled = s * c_invfact[tid + 1];
            addr = smem_u32(&sMomA[tid][h]);
        } else {                                          // B_{tid-4}
            scaled = s * c_invfact[tid - (NP - 1)];
            addr = smem_u32(&sMomB[tid - (NP - 1)][h]);
        }
#pragma unroll
        for (int r = 0; r < HEADS; r++) dsmem_store(addr, (uint32_t)r, scaled);
    }

    // -------- Cluster barrier: release our stores / acquire peers' ----------
    asm volatile("barrier.cluster.arrive.aligned;" ::: "memory");
    asm volatile("barrier.cluster.wait.aligned;"   ::: "memory");

    // -------- Phase 2: 4 heads per thread, packed head-pair Horner ----------
    const unsigned long long a0_2 = pk2(2048.0f, 2048.0f);       // A0/0! exact
    float acc = 0.0f;

#pragma unroll
    for (int p = 0; p < 2; p++) {
        const int H0 = half * 4 + 2 * p;                  // even -> aligned
        const int e0 = 2 * p;                             // local idx
        const unsigned long long q2 = pk2(qs[e0], qs[e0 + 1]);

        unsigned long long P0 = *(const unsigned long long*)&sMomA[NP - 2][H0];
#pragma unroll
        for (int n = NP - 3; n >= 0; n--)
            P0 = fma2(P0, q2, *(const unsigned long long*)&sMomA[n][H0]);
        P0 = fma2(P0, q2, a0_2);

        unsigned long long P1 = *(const unsigned long long*)&sMomB[NP - 1][H0];
#pragma unroll
        for (int n = NP - 2; n >= 0; n--)
            P1 = fma2(P1, q2, *(const unsigned long long*)&sMomB[n][H0]);

        float P0a, P0b, P1a, P1b;
        upk2(P0a, P0b, P0);
        upk2(P1a, P1b, P1);

        const float z0 = __fdividef(P1a - ev[e0],     P0a);
        const float z1 = __fdividef(P1b - ev[e0 + 1], P0b);
        acc = fmaf(z0, sW0[H0],     acc);
        acc = fmaf(z1, sW0[H0 + 1], acc);
    }

    sz[half][gl] = acc;
    __syncthreads();

    if (tid < 256)
        out[b * GENES + h * 256 + tid] = sz[0][tid] + sz[1][tid];
}

// ---------------------------------------------------------------------------
extern "C" void kernel_launch(void* const* d_in, const int* in_sizes, int n_in,
                              void* d_out, int out_size)
{
    const float* x  = (const float*)d_in[0];
    const float* WQ = (const float*)d_in[1];
    const float* WK = (const float*)d_in[2];
    const float* WV = (const float*)d_in[3];
    const float* W0 = (const float*)d_in[4];
    float* out = (float*)d_out;

    fused_attn_kernel<<<BATCH * HEADS, TPB>>>(x, WQ, WK, WV, W0, out);
}